// round 16
// baseline (speedup 1.0000x reference)
#include <cuda_runtime.h>
#include <cuda_fp16.h>
#include <math.h>
#include <stdint.h>

// Problem constants
#define B_   32
#define F_   128
#define T_   4000
#define H_   256     // hidden
#define O_   512     // 4F
#define KDIM 256     // 2F
#define EPS  1e-6f

// Scan chunking: 125 chunks of 32 -> 4000
#define CHUNK 32
#define NC    125
#define CHAIN_SMEM (NC * F_ * 2 * 4)   // 128000 B

// Fused MLP geometry: BM=64 rows/CTA, 256 threads, 2 CTAs/SM
//  A panels : 8 x (64 rows x 64B)  = 32768  at 0        (X, K32 per panel)
//  B slots  : 3 x (256 rows x 64B) = 49152  at 32768    (W1, K32 per slot)
//  h panels : 4 x (64 rows x 128B) = 32768  at 81920    (K64 per panel)
//  phase2 W2 buffer: 4 x (128 rows x 128B) = 65536 at 0 (aliases A+B slots 0,1)
#define A_OFF   0
#define B_OFF   32768
#define H2_OFF  81920
#define SMEM_FUSED 114688

// ---------------------------------------------------------------------------
// Scratch (device globals)
// ---------------------------------------------------------------------------
__device__ __align__(128) __half  g_Xf  [B_ * T_ * F_];   // fp16 [b][t][f]
__device__ __align__(128) __half  g_W1f [H_ * KDIM];
__device__ __align__(128) __half  g_W2f [O_ * KDIM];
__device__ __align__(128) __half  g_actH[B_ * T_ * O_];   // fp16 activations
__device__ float g_Ac[B_ * NC * F_];    // [b][c][f]
__device__ float g_Bc[B_ * NC * F_];
__device__ float g_Ms[B_ * NC * F_];

// ---------------------------------------------------------------------------
// Helpers
// ---------------------------------------------------------------------------
__device__ __forceinline__ uint32_t smem_u32(const void* p) {
    uint32_t a;
    asm("{ .reg .u64 t; cvta.to.shared.u64 t, %1; cvt.u32.u64 %0, t; }" : "=r"(a) : "l"(p));
    return a;
}
__device__ __forceinline__ void cp16(uint32_t dst, const void* src) {
    asm volatile("cp.async.cg.shared.global [%0], [%1], 16;" :: "r"(dst), "l"(src) : "memory");
}
#define CP_COMMIT() asm volatile("cp.async.commit_group;" ::: "memory")
#define CP_WAIT1()  asm volatile("cp.async.wait_group 1;" ::: "memory")
#define CP_WAIT0()  asm volatile("cp.async.wait_group 0;" ::: "memory")

__device__ __forceinline__ void ldsm_x4(uint32_t& r0, uint32_t& r1, uint32_t& r2, uint32_t& r3,
                                        uint32_t addr) {
    asm volatile("ldmatrix.sync.aligned.m8n8.x4.shared.b16 {%0,%1,%2,%3}, [%4];"
                 : "=r"(r0), "=r"(r1), "=r"(r2), "=r"(r3) : "r"(addr));
}
__device__ __forceinline__ void mma_fp16(float* c, const uint32_t* a, const uint32_t* b) {
    asm volatile("mma.sync.aligned.m16n8k16.row.col.f32.f16.f16.f32 "
                 "{%0,%1,%2,%3}, {%4,%5,%6,%7}, {%8,%9}, {%0,%1,%2,%3};"
                 : "+f"(c[0]), "+f"(c[1]), "+f"(c[2]), "+f"(c[3])
                 : "r"(a[0]), "r"(a[1]), "r"(a[2]), "r"(a[3]), "r"(b[0]), "r"(b[1]));
}
__device__ __forceinline__ uint32_t pack_h2(float x, float y) {
    __half2 h = __floats2half2_rn(x, y);
    return *(uint32_t*)&h;
}
__device__ __forceinline__ float sigmoid_tanh(float x) {
    float t;
    asm("tanh.approx.f32 %0, %1;" : "=f"(t) : "f"(x * 0.5f));
    return fmaf(t, 0.5f, 0.5f);
}

// ---------------------------------------------------------------------------
// Transpose + fp16 convert: in [R][C] fp32 -> out [C][R] fp16  (X path)
// ---------------------------------------------------------------------------
__global__ void transpose_conv(const float* __restrict__ in, __half* __restrict__ outH,
                               int R, int C) {
    __shared__ float tile[32][33];
    size_t boff = (size_t)blockIdx.z * R * C;
    in += boff;
    int c0 = blockIdx.x * 32, r0 = blockIdx.y * 32;
    int x = threadIdx.x, y = threadIdx.y;
    #pragma unroll
    for (int i = 0; i < 32; i += 8)
        tile[y + i][x] = in[(size_t)(r0 + y + i) * C + c0 + x];
    __syncthreads();
    #pragma unroll
    for (int i = 0; i < 32; i += 8) {
        float v = tile[x][y + i];
        outH[boff + (size_t)(c0 + y + i) * R + r0 + x] = __float2half_rn(v);
    }
}

// ---------------------------------------------------------------------------
// Merged W1+W2 transpose
// ---------------------------------------------------------------------------
__global__ void transpose_w(const float* __restrict__ W1, __half* __restrict__ W1f,
                            const float* __restrict__ W2, __half* __restrict__ W2f) {
    __shared__ float tile[32][33];
    const int z = blockIdx.z;
    const int C = z ? O_ : H_;
    if (blockIdx.x * 32 >= C) return;
    const float* in = z ? W2 : W1;
    __half* outH    = z ? W2f : W1f;
    int c0 = blockIdx.x * 32, r0 = blockIdx.y * 32;
    int x = threadIdx.x, y = threadIdx.y;
    #pragma unroll
    for (int i = 0; i < 32; i += 8)
        tile[y + i][x] = in[(size_t)(r0 + y + i) * C + c0 + x];
    __syncthreads();
    #pragma unroll
    for (int i = 0; i < 32; i += 8) {
        float v = tile[x][y + i];
        outH[(size_t)(c0 + y + i) * KDIM + r0 + x] = __float2half_rn(v);
    }
}

// ---------------------------------------------------------------------------
// Fused MLP, BM=64, 256 threads, 2 CTAs/SM.
// Phase 1: h(64x256) = relu(concat(X[:,t-1],X[:,t]) @ W1 + b1) -> smem fp16
// Phase 2: actH(64x512) = activation(h @ W2 + b2)              -> global
// ---------------------------------------------------------------------------
__global__ __launch_bounds__(256, 2) void fused_mlp(const float* __restrict__ b1,
                                                    const float* __restrict__ b2) {
    extern __shared__ __align__(128) char sm[];
    const int tid = threadIdx.x;
    const int lane = tid & 31;
    const int wid = tid >> 5;          // 0..7
    const int wm = wid >> 2;           // 0..1
    const int wn = wid & 3;            // 0..3
    const int m0 = blockIdx.x * 64;
    const uint32_t base = smem_u32(sm);

    // 64B-row staging ids (A panels / W1 slots): 1 row per thread
    const int s4_row = tid >> 2;       // 0..63
    const int s4_k   = tid & 3;
    const uint32_t s4_d = (uint32_t)s4_row * 64 + (((uint32_t)s4_k ^ ((uint32_t)(s4_row >> 1) & 3)) << 4);
    // 128B-row staging ids (W2 buffers)
    const int s8_row = tid >> 3;       // 0..31
    const int s8_k   = tid & 7;
    const uint32_t s8_d = (uint32_t)s8_row * 128 + (((uint32_t)s8_k ^ (uint32_t)(s8_row & 7)) << 4);

    // per-row X addresses (row = m0 + s4_row)
    size_t acur, aprev;
    {
        int gr = m0 + s4_row;
        int b = gr / T_;
        int t = gr - b * T_;
        int tp = t ? t - 1 : 0;
        acur  = ((size_t)b * T_ + t)  * F_ + s4_k * 8;
        aprev = ((size_t)b * T_ + tp) * F_ + s4_k * 8;
    }

    // ldmatrix addressing
    const uint32_t a_rowb  = (uint32_t)(wm * 32) + (lane & 15);
    const uint32_t a_half  = (uint32_t)lane >> 4;
    const uint32_t sw4_a   = (a_rowb >> 1) & 3;
    const uint32_t sw8_a   = a_rowb & 7;
    const uint32_t b1_rowb = (uint32_t)(wn * 64) + (((uint32_t)lane >> 4) << 3) + (lane & 7);
    const uint32_t sw4_b1  = (b1_rowb >> 1) & 3;
    const uint32_t b2_rowb = (uint32_t)(wn * 32) + (((uint32_t)lane >> 4) << 3) + (lane & 7);
    const uint32_t sw8_b2  = b2_rowb & 7;
    const uint32_t b_half  = ((uint32_t)lane >> 3) & 1;
    const int rloc  = lane >> 2;
    const int cpair = (lane & 3) * 2;

    // ---------------- Phase 1 ----------------
    // Stage all 8 A panels (K32 each: c<4 prev-frame, c>=4 cur-frame)
    #pragma unroll
    for (int c = 0; c < 8; c++) {
        size_t so = (c < 4) ? (aprev + c * 32) : (acur + (c - 4) * 32);
        cp16(base + A_OFF + c * 4096 + s4_d, g_Xf + so);
    }
    // W1 chunk staging: 256 rows x K32, 4 cp16/thread
    auto stageB1 = [&](int c, int slot) {
        uint32_t dst = base + B_OFF + slot * 16384;
        #pragma unroll
        for (int p = 0; p < 4; p++)
            cp16(dst + s4_d + p * (64 * 64),
                 g_W1f + (size_t)(s4_row + 64 * p) * KDIM + c * 32 + s4_k * 8);
    };
    stageB1(0, 0); CP_COMMIT();     // group0: A + B0
    stageB1(1, 1); CP_COMMIT();     // group1: B1

    float acc1[2][8][4];
    #pragma unroll
    for (int i = 0; i < 2; i++)
        #pragma unroll
        for (int j = 0; j < 8; j++)
            #pragma unroll
            for (int q = 0; q < 4; q++) acc1[i][j][q] = 0.f;

    #pragma unroll 1
    for (int c = 0; c < 8; c++) {
        CP_WAIT1();
        __syncthreads();
        if (c + 2 < 8) stageB1(c + 2, (c + 2) % 3);
        CP_COMMIT();

        const uint32_t pA = base + A_OFF + c * 4096;
        const uint32_t pB = base + B_OFF + (c % 3) * 16384;
        #pragma unroll
        for (int s = 0; s < 2; s++) {
            const uint32_t a_co = ((2 * s + a_half) ^ sw4_a) << 4;
            const uint32_t b_co = ((2 * s + b_half) ^ sw4_b1) << 4;
            uint32_t bf[8][2];
            #pragma unroll
            for (int jj = 0; jj < 4; jj++) {
                uint32_t r0, r1, r2, r3;
                ldsm_x4(r0, r1, r2, r3, pB + (b1_rowb + jj * 16) * 64 + b_co);
                bf[2 * jj][0] = r0;     bf[2 * jj][1] = r1;
                bf[2 * jj + 1][0] = r2; bf[2 * jj + 1][1] = r3;
            }
            #pragma unroll
            for (int i = 0; i < 2; i++) {
                uint32_t af[4];
                ldsm_x4(af[0], af[1], af[2], af[3], pA + (a_rowb + i * 16) * 64 + a_co);
                #pragma unroll
                for (int j = 0; j < 8; j++)
                    mma_fp16(acc1[i][j], af, bf[j]);
            }
        }
    }

    // h epilogue -> smem panels (128B rows, 8-chunk swizzle)
    #pragma unroll
    for (int i = 0; i < 2; i++) {
        int r0 = wm * 32 + i * 16 + rloc;
        #pragma unroll
        for (int j = 0; j < 8; j++) {
            int ng = wn * 64 + j * 8 + cpair;
            float2 bb = *(const float2*)&b1[ng];
            float u0 = fmaxf(acc1[i][j][0] + bb.x, 0.f);
            float u1 = fmaxf(acc1[i][j][1] + bb.y, 0.f);
            float u2 = fmaxf(acc1[i][j][2] + bb.x, 0.f);
            float u3 = fmaxf(acc1[i][j][3] + bb.y, 0.f);
            int panel = ng >> 6, cp = ng & 63;
            uint32_t o0 = H2_OFF + panel * 8192 + (uint32_t)r0 * 128
                        + (((uint32_t)(cp >> 3) ^ (uint32_t)(r0 & 7)) << 4) + (uint32_t)(cp & 7) * 2;
            *(uint32_t*)(sm + o0)           = pack_h2(u0, u1);
            *(uint32_t*)(sm + o0 + 8 * 128) = pack_h2(u2, u3);
        }
    }
    __syncthreads();   // h complete; A/B region safe to reuse

    // ---------------- Phase 2: 4 n-chunks of 128 cols, single 64KB buffer ----------------
    #pragma unroll 1
    for (int nc = 0; nc < 4; nc++) {
        // stage W2 chunk: rows nc*128..+127, 4 kk panels of 128 rows x 128B
        #pragma unroll
        for (int kk = 0; kk < 4; kk++)
            #pragma unroll
            for (int p = 0; p < 4; p++)
                cp16(base + kk * 16384 + s8_d + p * (32 * 128),
                     g_W2f + (size_t)(nc * 128 + s8_row + 32 * p) * KDIM + kk * 64 + s8_k * 8);
        CP_COMMIT();
        CP_WAIT0();
        __syncthreads();

        float acc2[2][4][4];
        #pragma unroll
        for (int i = 0; i < 2; i++)
            #pragma unroll
            for (int j = 0; j < 4; j++)
                #pragma unroll
                for (int q = 0; q < 4; q++) acc2[i][j][q] = 0.f;

        #pragma unroll
        for (int kk = 0; kk < 4; kk++) {
            const uint32_t pA = base + H2_OFF + kk * 8192;
            const uint32_t pB = base + kk * 16384;
            #pragma unroll
            for (int s = 0; s < 4; s++) {
                const uint32_t a_co = ((2 * s + a_half) ^ sw8_a) << 4;
                const uint32_t b_co = ((2 * s + b_half) ^ sw8_b2) << 4;
                uint32_t bf[4][2];
                #pragma unroll
                for (int jj = 0; jj < 2; jj++) {
                    uint32_t r0, r1, r2, r3;
                    ldsm_x4(r0, r1, r2, r3, pB + (b2_rowb + jj * 16) * 128 + b_co);
                    bf[2 * jj][0] = r0;     bf[2 * jj][1] = r1;
                    bf[2 * jj + 1][0] = r2; bf[2 * jj + 1][1] = r3;
                }
                #pragma unroll
                for (int i = 0; i < 2; i++) {
                    uint32_t af[4];
                    ldsm_x4(af[0], af[1], af[2], af[3], pA + (a_rowb + i * 16) * 128 + a_co);
                    #pragma unroll
                    for (int j = 0; j < 4; j++)
                        mma_fp16(acc2[i][j], af, bf[j]);
                }
            }
        }

        const bool sp = (nc == 2);   // cols [256,384): softplus (delta)
        #pragma unroll
        for (int i = 0; i < 2; i++) {
            int r0 = m0 + wm * 32 + i * 16 + rloc;
            int r1 = r0 + 8;
            #pragma unroll
            for (int j = 0; j < 4; j++) {
                int ng = nc * 128 + wn * 32 + j * 8 + cpair;
                float2 bb = *(const float2*)&b2[ng];
                float uu[4] = {acc2[i][j][0] + bb.x, acc2[i][j][1] + bb.y,
                               acc2[i][j][2] + bb.x, acc2[i][j][3] + bb.y};
                float v[4];
                #pragma unroll
                for (int q = 0; q < 4; q++) {
                    float u = uu[q];
                    v[q] = sp ? (__logf(1.f + __expf(-fabsf(u))) + fmaxf(u, 0.f))
                              : sigmoid_tanh(u);
                }
                *(uint32_t*)&g_actH[(size_t)r0 * O_ + ng] = pack_h2(v[0], v[1]);
                *(uint32_t*)&g_actH[(size_t)r1 * O_ + ng] = pack_h2(v[2], v[3]);
            }
        }
        __syncthreads();   // all reads of buffer done before next stage overwrites
    }
}

// ---------------------------------------------------------------------------
// Scan stage A: per-chunk composition  (writes [b][c][f], fully coalesced)
// ---------------------------------------------------------------------------
__global__ __launch_bounds__(256) void scan_reduce_kernel() {
    int id = blockIdx.x * blockDim.x + threadIdx.x;
    int f = id & (F_ - 1);
    int r = id >> 7;
    int c = r % NC;
    int b = r / NC;

    const __half* actb = g_actH + (size_t)(b * T_) * O_;
    const __half* Xfb  = g_Xf + (size_t)b * T_ * F_;

    float A = 1.f, Bv = 0.f;
    int t0 = c * CHUNK;
    #pragma unroll 4
    for (int t = t0; t < t0 + CHUNK; t++) {
        float s = __half2float(actb[(size_t)t * O_ + f]);
        float x = __half2float(Xfb[(size_t)t * F_ + f]);
        float a = 1.f - s;
        A  *= a;
        Bv = a * Bv + s * x;
    }
    g_Ac[id] = A;
    g_Bc[id] = Bv;
}

// ---------------------------------------------------------------------------
// Scan stage B: per-(b,f) chain over NC chunk summaries, smem-cached.
// ---------------------------------------------------------------------------
__global__ __launch_bounds__(128) void scan_chain_kernel() {
    extern __shared__ float chsm[];              // As[NC*F_], Bs[NC*F_]
    float* As = chsm;
    float* Bs = chsm + NC * F_;
    int b = blockIdx.x, f = threadIdx.x;
    int base = b * NC * F_;

    for (int i = f; i < NC * F_; i += 128) {
        As[i] = g_Ac[base + i];
        Bs[i] = g_Bc[base + i];
    }
    __syncthreads();

    float M = 0.f;
    #pragma unroll 5
    for (int c = 0; c < NC; c++) {
        g_Ms[base + c * F_ + f] = M;
        M = As[c * F_ + f] * M + Bs[c * F_ + f];
    }
}

// ---------------------------------------------------------------------------
// Scan stage C: replay + PCEN epilogue; one 32x128 transpose tile per CTA.
// ---------------------------------------------------------------------------
__global__ __launch_bounds__(128) void scan_final_kernel(float* __restrict__ out) {
    __shared__ float tile[32][129];
    int bc = blockIdx.x;
    int b = bc / NC;
    int c = bc % NC;
    int f = threadIdx.x;
    int lane = f & 31, wid = f >> 5;

    const __half* actb = g_actH + (size_t)(b * T_) * O_;
    const __half* Xfb  = g_Xf + (size_t)b * T_ * F_;

    float M = g_Ms[(b * NC + c) * F_ + f];
    int t0 = c * CHUNK;
    #pragma unroll 4
    for (int q = 0; q < CHUNK; q++) {
        int t = t0 + q;
        const __half* rowp = actb + (size_t)t * O_;
        float s     = __half2float(rowp[f]);
        float alpha = __half2float(rowp[128 + f]);
        float delta = __half2float(rowp[256 + f]);
        float r     = __half2float(rowp[384 + f]);
        float x = __half2float(Xfb[(size_t)t * F_ + f]);
        M = (1.f - s) * M + s * x;
        float base = x * __powf(M + EPS, -alpha) + delta;
        tile[q][f] = __powf(base, r) - __powf(delta, r);
    }
    __syncthreads();
    #pragma unroll
    for (int ff = wid; ff < 128; ff += 4)
        out[(size_t)(b * F_ + ff) * T_ + t0 + lane] = tile[lane][ff];
}

// ---------------------------------------------------------------------------
// Launch
// ---------------------------------------------------------------------------
extern "C" void kernel_launch(void* const* d_in, const int* in_sizes, int n_in,
                              void* d_out, int out_size) {
    const float* X  = (const float*)d_in[0];
    const float* W1 = (const float*)d_in[1];
    const float* b1 = (const float*)d_in[2];
    const float* W2 = (const float*)d_in[3];
    const float* b2 = (const float*)d_in[4];
    float* out = (float*)d_out;

    __half *Xf, *W1f, *W2f;
    cudaGetSymbolAddress((void**)&Xf,  g_Xf);
    cudaGetSymbolAddress((void**)&W1f, g_W1f);
    cudaGetSymbolAddress((void**)&W2f, g_W2f);

    // Idempotent host-side attribute sets (capture-safe)
    cudaFuncSetAttribute(fused_mlp, cudaFuncAttributeMaxDynamicSharedMemorySize, SMEM_FUSED);
    cudaFuncSetAttribute(scan_chain_kernel, cudaFuncAttributeMaxDynamicSharedMemorySize, CHAIN_SMEM);

    transpose_conv<<<dim3(T_ / 32, F_ / 32, B_), dim3(32, 8)>>>(X, Xf, F_, T_);
    transpose_w<<<dim3(O_ / 32, KDIM / 32, 2), dim3(32, 8)>>>(W1, W1f, W2, W2f);

    fused_mlp<<<(B_ * T_) / 64, 256, SMEM_FUSED>>>(b1, b2);   // 2000 CTAs

    scan_reduce_kernel<<<(B_ * NC * F_) / 256, 256>>>();
    scan_chain_kernel<<<B_, 128, CHAIN_SMEM>>>();
    scan_final_kernel<<<B_ * NC, 128>>>(out);
}

// round 17
// speedup vs baseline: 1.0330x; 1.0330x over previous
#include <cuda_runtime.h>
#include <cuda_fp16.h>
#include <math.h>
#include <stdint.h>

// Problem constants
#define B_   32
#define F_   128
#define T_   4000
#define H_   256     // hidden
#define O_   512     // 4F
#define KDIM 256     // 2F
#define EPS  1e-6f

// Scan chunking: 125 chunks of 32 -> 4000
#define CHUNK 32
#define NC    125
#define CHAIN_SMEM (NC * F_ * 2 * 4)   // 128000 B

// Fused MLP kernel geometry (round-15 proven config)
#define SLOT_BYTES 49152              // phase1 stage: A 16KB + B 32KB
#define H_OFF      147456             // h panels after 3 stage slots
#define SMEM_FUSED (H_OFF + 65536)    // 212992 B (208 KB)

// ---------------------------------------------------------------------------
// Scratch (device globals)
// ---------------------------------------------------------------------------
__device__ __align__(128) __half  g_Xf  [B_ * T_ * F_];   // fp16 [b][t][f]
__device__ __align__(128) __half  g_W1f [H_ * KDIM];
__device__ __align__(128) __half  g_W2f [O_ * KDIM];
__device__ __align__(128) __half  g_actH[B_ * T_ * O_];   // fp16 activations
__device__ float g_Ac[B_ * NC * F_];    // [b][c][f]
__device__ float g_Bc[B_ * NC * F_];
__device__ float g_Ms[B_ * NC * F_];

// ---------------------------------------------------------------------------
// Helpers
// ---------------------------------------------------------------------------
__device__ __forceinline__ uint32_t smem_u32(const void* p) {
    uint32_t a;
    asm("{ .reg .u64 t; cvta.to.shared.u64 t, %1; cvt.u32.u64 %0, t; }" : "=r"(a) : "l"(p));
    return a;
}
__device__ __forceinline__ void cp16(uint32_t dst, const void* src) {
    asm volatile("cp.async.cg.shared.global [%0], [%1], 16;" :: "r"(dst), "l"(src) : "memory");
}
#define CP_COMMIT() asm volatile("cp.async.commit_group;" ::: "memory")
#define CP_WAIT1()  asm volatile("cp.async.wait_group 1;" ::: "memory")

__device__ __forceinline__ void ldsm_x4(uint32_t& r0, uint32_t& r1, uint32_t& r2, uint32_t& r3,
                                        uint32_t addr) {
    asm volatile("ldmatrix.sync.aligned.m8n8.x4.shared.b16 {%0,%1,%2,%3}, [%4];"
                 : "=r"(r0), "=r"(r1), "=r"(r2), "=r"(r3) : "r"(addr));
}
__device__ __forceinline__ void mma_fp16(float* c, const uint32_t* a, const uint32_t* b) {
    asm volatile("mma.sync.aligned.m16n8k16.row.col.f32.f16.f16.f32 "
                 "{%0,%1,%2,%3}, {%4,%5,%6,%7}, {%8,%9}, {%0,%1,%2,%3};"
                 : "+f"(c[0]), "+f"(c[1]), "+f"(c[2]), "+f"(c[3])
                 : "r"(a[0]), "r"(a[1]), "r"(a[2]), "r"(a[3]), "r"(b[0]), "r"(b[1]));
}
__device__ __forceinline__ uint32_t pack_h2(float x, float y) {
    __half2 h = __floats2half2_rn(x, y);
    return *(uint32_t*)&h;
}
__device__ __forceinline__ float sigmoid_tanh(float x) {
    float t;
    asm("tanh.approx.f32 %0, %1;" : "=f"(t) : "f"(x * 0.5f));
    return fmaf(t, 0.5f, 0.5f);
}

// ---------------------------------------------------------------------------
// Transpose + fp16 convert: in [R][C] fp32 -> out [C][R] fp16  (X path)
// ---------------------------------------------------------------------------
__global__ void transpose_conv(const float* __restrict__ in, __half* __restrict__ outH,
                               int R, int C) {
    __shared__ float tile[32][33];
    size_t boff = (size_t)blockIdx.z * R * C;
    in += boff;
    int c0 = blockIdx.x * 32, r0 = blockIdx.y * 32;
    int x = threadIdx.x, y = threadIdx.y;
    #pragma unroll
    for (int i = 0; i < 32; i += 8)
        tile[y + i][x] = in[(size_t)(r0 + y + i) * C + c0 + x];
    __syncthreads();
    #pragma unroll
    for (int i = 0; i < 32; i += 8) {
        float v = tile[x][y + i];
        outH[boff + (size_t)(c0 + y + i) * R + r0 + x] = __float2half_rn(v);
    }
}

// ---------------------------------------------------------------------------
// Merged W1+W2 transpose
// ---------------------------------------------------------------------------
__global__ void transpose_w(const float* __restrict__ W1, __half* __restrict__ W1f,
                            const float* __restrict__ W2, __half* __restrict__ W2f) {
    __shared__ float tile[32][33];
    const int z = blockIdx.z;
    const int C = z ? O_ : H_;
    if (blockIdx.x * 32 >= C) return;
    const float* in = z ? W2 : W1;
    __half* outH    = z ? W2f : W1f;
    int c0 = blockIdx.x * 32, r0 = blockIdx.y * 32;
    int x = threadIdx.x, y = threadIdx.y;
    #pragma unroll
    for (int i = 0; i < 32; i += 8)
        tile[y + i][x] = in[(size_t)(r0 + y + i) * C + c0 + x];
    __syncthreads();
    #pragma unroll
    for (int i = 0; i < 32; i += 8) {
        float v = tile[x][y + i];
        outH[(size_t)(c0 + y + i) * KDIM + r0 + x] = __float2half_rn(v);
    }
}

// ---------------------------------------------------------------------------
// Fused MLP (round-15 config): one CTA per 128 rows, 512 threads, 208KB smem.
// Phase 1: h(128x256) = relu(concat(X[:,t-1],X[:,t]) @ W1 + b1)  -> SMEM fp16
// Phase 2: actH(128x512) = activation(h @ W2 + b2)               -> global
// NEW: nc=0's W2 chunk prefetched during last phase-1 K-chunk (slots 1-2 dead);
//      phase-2 buffer parity flipped so in-order group completion matches waits.
// ---------------------------------------------------------------------------
__global__ __launch_bounds__(512, 1) void fused_mlp(const float* __restrict__ b1,
                                                    const float* __restrict__ b2) {
    extern __shared__ __align__(128) char sm[];
    const int tid = threadIdx.x;
    const int lane = tid & 31;
    const int wid = tid >> 5;          // 0..15
    const int wm = wid >> 2;           // 0..3
    const int wn = wid & 3;            // 0..3
    const int m0 = blockIdx.x * 128;
    const uint32_t base = smem_u32(sm);

    const int st_row = tid >> 3;
    const int st_k   = tid & 7;
    const uint32_t st_off = (uint32_t)st_row * 128 + (((uint32_t)st_k ^ (uint32_t)(st_row & 7)) << 4);

    size_t acur[2], aprev[2];
    #pragma unroll
    for (int p = 0; p < 2; p++) {
        int gr = m0 + st_row + 64 * p;
        int b = gr / T_;
        int t = gr - b * T_;
        int tp = t ? t - 1 : 0;
        acur[p]  = ((size_t)b * T_ + t)  * F_ + st_k * 8;
        aprev[p] = ((size_t)b * T_ + tp) * F_ + st_k * 8;
    }

    auto stage1 = [&](int c, int slot) {
        uint32_t sA = base + slot * SLOT_BYTES;
        const int k0 = c * 64;
        #pragma unroll
        for (int p = 0; p < 2; p++) {
            size_t so = (c < 2) ? (aprev[p] + k0) : (acur[p] + (k0 - 128));
            cp16(sA + st_off + p * 8192, g_Xf + so);
        }
        #pragma unroll
        for (int p = 0; p < 4; p++)
            cp16(sA + 16384 + st_off + p * 8192,
                 g_W1f + (size_t)(st_row + 64 * p) * KDIM + k0 + st_k * 8);
    };

    auto stage2 = [&](int nc, uint32_t buf) {
        #pragma unroll
        for (int kk = 0; kk < 4; kk++)
            #pragma unroll
            for (int p = 0; p < 2; p++)
                cp16(buf + kk * 16384 + st_off + p * 8192,
                     g_W2f + (size_t)(nc * 128 + st_row + 64 * p) * KDIM + kk * 64 + st_k * 8);
    };

    const uint32_t a_rowb  = (uint32_t)(wm * 32) + (lane & 15);
    const uint32_t a_half  = (uint32_t)lane >> 4;
    const uint32_t sw_a    = a_rowb & 7;
    const uint32_t b1_rowb = (uint32_t)(wn * 64) + (((uint32_t)lane >> 4) << 3) + (lane & 7);
    const uint32_t b2_rowb = (uint32_t)(wn * 32) + (((uint32_t)lane >> 4) << 3) + (lane & 7);
    const uint32_t b_half  = ((uint32_t)lane >> 3) & 1;
    const uint32_t sw_b1   = b1_rowb & 7;
    const uint32_t sw_b2   = b2_rowb & 7;
    const int rloc  = lane >> 2;
    const int cpair = (lane & 3) * 2;

    // ---------------- Phase 1 ----------------
    float acc1[2][8][4];
    #pragma unroll
    for (int i = 0; i < 2; i++)
        #pragma unroll
        for (int j = 0; j < 8; j++)
            #pragma unroll
            for (int q = 0; q < 4; q++) acc1[i][j][q] = 0.f;

    stage1(0, 0); CP_COMMIT();
    stage1(1, 1); CP_COMMIT();

    #pragma unroll 1
    for (int c = 0; c < 4; c++) {
        CP_WAIT1();
        __syncthreads();
        if (c + 2 < 4) stage1(c + 2, (c + 2) % 3);
        if (c == 3) stage2(0, base + 65536);   // early W2 prefetch into dead slots 1-2
        CP_COMMIT();

        const uint32_t sA = base + (c % 3) * SLOT_BYTES;
        const uint32_t sB = sA + 16384;
        #pragma unroll
        for (int s = 0; s < 4; s++) {
            const uint32_t a_co = ((2 * s + a_half) ^ sw_a) << 4;
            const uint32_t b_co = ((2 * s + b_half) ^ sw_b1) << 4;
            uint32_t bf[8][2];
            #pragma unroll
            for (int jj = 0; jj < 4; jj++) {
                uint32_t r0, r1, r2, r3;
                ldsm_x4(r0, r1, r2, r3, sB + (b1_rowb + jj * 16) * 128 + b_co);
                bf[2 * jj][0] = r0;     bf[2 * jj][1] = r1;
                bf[2 * jj + 1][0] = r2; bf[2 * jj + 1][1] = r3;
            }
            #pragma unroll
            for (int i = 0; i < 2; i++) {
                uint32_t af[4];
                ldsm_x4(af[0], af[1], af[2], af[3], sA + (a_rowb + i * 16) * 128 + a_co);
                #pragma unroll
                for (int j = 0; j < 8; j++)
                    mma_fp16(acc1[i][j], af, bf[j]);
            }
        }
    }

    // h epilogue -> smem panels
    #pragma unroll
    for (int i = 0; i < 2; i++) {
        int r0 = wm * 32 + i * 16 + rloc;
        #pragma unroll
        for (int j = 0; j < 8; j++) {
            int ng = wn * 64 + j * 8 + cpair;
            float2 bb = *(const float2*)&b1[ng];
            float u0 = fmaxf(acc1[i][j][0] + bb.x, 0.f);
            float u1 = fmaxf(acc1[i][j][1] + bb.y, 0.f);
            float u2 = fmaxf(acc1[i][j][2] + bb.x, 0.f);
            float u3 = fmaxf(acc1[i][j][3] + bb.y, 0.f);
            int panel = ng >> 6, cp = ng & 63;
            uint32_t o0 = H_OFF + panel * 16384 + (uint32_t)r0 * 128
                        + (((uint32_t)(cp >> 3) ^ (uint32_t)(r0 & 7)) << 4) + (uint32_t)(cp & 7) * 2;
            *(uint32_t*)(sm + o0)           = pack_h2(u0, u1);
            *(uint32_t*)(sm + o0 + 8 * 128) = pack_h2(u2, u3);
        }
    }
    __syncthreads();

    // ---------------- Phase 2 ----------------
    // Group order: G0 = nc0 W2 (region base+65536, issued at c=3), G1 = nc1 (base).
    stage2(1, base);  CP_COMMIT();

    #pragma unroll 1
    for (int nc = 0; nc < 4; nc++) {
        CP_WAIT1();                  // in-order completion: oldest pending group done
        __syncthreads();
        const uint32_t bbuf = base + (uint32_t)((nc & 1) ^ 1) * 65536;

        float acc2[2][4][4];
        #pragma unroll
        for (int i = 0; i < 2; i++)
            #pragma unroll
            for (int j = 0; j < 4; j++)
                #pragma unroll
                for (int q = 0; q < 4; q++) acc2[i][j][q] = 0.f;

        #pragma unroll
        for (int kk = 0; kk < 4; kk++) {
            const uint32_t hA = base + H_OFF + kk * 16384;
            const uint32_t sB = bbuf + kk * 16384;
            #pragma unroll
            for (int s = 0; s < 4; s++) {
                const uint32_t a_co = ((2 * s + a_half) ^ sw_a) << 4;
                const uint32_t b_co = ((2 * s + b_half) ^ sw_b2) << 4;
                uint32_t bf[4][2];
                #pragma unroll
                for (int jj = 0; jj < 2; jj++) {
                    uint32_t r0, r1, r2, r3;
                    ldsm_x4(r0, r1, r2, r3, sB + (b2_rowb + jj * 16) * 128 + b_co);
                    bf[2 * jj][0] = r0;     bf[2 * jj][1] = r1;
                    bf[2 * jj + 1][0] = r2; bf[2 * jj + 1][1] = r3;
                }
                #pragma unroll
                for (int i = 0; i < 2; i++) {
                    uint32_t af[4];
                    ldsm_x4(af[0], af[1], af[2], af[3], hA + (a_rowb + i * 16) * 128 + a_co);
                    #pragma unroll
                    for (int j = 0; j < 4; j++)
                        mma_fp16(acc2[i][j], af, bf[j]);
                }
            }
        }

        const bool sp = (nc == 2);   // cols [256,384): softplus (delta)
        #pragma unroll
        for (int i = 0; i < 2; i++) {
            int r0 = m0 + wm * 32 + i * 16 + rloc;
            int r1 = r0 + 8;
            #pragma unroll
            for (int j = 0; j < 4; j++) {
                int ng = nc * 128 + wn * 32 + j * 8 + cpair;
                float2 bb = *(const float2*)&b2[ng];
                float uu[4] = {acc2[i][j][0] + bb.x, acc2[i][j][1] + bb.y,
                               acc2[i][j][2] + bb.x, acc2[i][j][3] + bb.y};
                float v[4];
                #pragma unroll
                for (int q = 0; q < 4; q++) {
                    float u = uu[q];
                    v[q] = sp ? (__logf(1.f + __expf(-fabsf(u))) + fmaxf(u, 0.f))
                              : sigmoid_tanh(u);
                }
                *(uint32_t*)&g_actH[(size_t)r0 * O_ + ng] = pack_h2(v[0], v[1]);
                *(uint32_t*)&g_actH[(size_t)r1 * O_ + ng] = pack_h2(v[2], v[3]);
            }
        }
        __syncthreads();
        if (nc + 2 < 4) stage2(nc + 2, bbuf);   // restage just-read buffer
        CP_COMMIT();
    }
}

// ---------------------------------------------------------------------------
// Scan stage A: per-chunk composition, half2 f-pairs (writes [b][c][f])
// grid 1000 x 256 threads; thread = (b, c, f-pair)
// ---------------------------------------------------------------------------
__global__ __launch_bounds__(256) void scan_reduce_kernel() {
    int id = blockIdx.x * blockDim.x + threadIdx.x;   // 0 .. B*NC*64
    int f2 = id & 63;
    int r = id >> 6;
    int c = r % NC;
    int b = r / NC;

    const __half2* actb = (const __half2*)(g_actH + (size_t)(b * T_) * O_);
    const __half2* Xfb  = (const __half2*)(g_Xf + (size_t)b * T_ * F_);

    float2 A = {1.f, 1.f}, Bv = {0.f, 0.f};
    int t0 = c * CHUNK;
    #pragma unroll 4
    for (int t = t0; t < t0 + CHUNK; t++) {
        float2 s = __half22float2(actb[(size_t)t * (O_ / 2) + f2]);
        float2 x = __half22float2(Xfb[(size_t)t * (F_ / 2) + f2]);
        float ax = 1.f - s.x, ay = 1.f - s.y;
        A.x *= ax;  Bv.x = ax * Bv.x + s.x * x.x;
        A.y *= ay;  Bv.y = ay * Bv.y + s.y * x.y;
    }
    *(float2*)&g_Ac[r * F_ + 2 * f2] = A;
    *(float2*)&g_Bc[r * F_ + 2 * f2] = Bv;
}

// ---------------------------------------------------------------------------
// Scan stage B: per-(b,f) chain over NC chunk summaries, smem-cached.
// ---------------------------------------------------------------------------
__global__ __launch_bounds__(128) void scan_chain_kernel() {
    extern __shared__ float chsm[];              // As[NC*F_], Bs[NC*F_]
    float* As = chsm;
    float* Bs = chsm + NC * F_;
    int b = blockIdx.x, f = threadIdx.x;
    int base = b * NC * F_;

    for (int i = f; i < NC * F_; i += 128) {
        As[i] = g_Ac[base + i];
        Bs[i] = g_Bc[base + i];
    }
    __syncthreads();

    float M = 0.f;
    #pragma unroll 5
    for (int c = 0; c < NC; c++) {
        g_Ms[base + c * F_ + f] = M;
        M = As[c * F_ + f] * M + Bs[c * F_ + f];
    }
}

// ---------------------------------------------------------------------------
// Scan stage C: replay + PCEN epilogue; one 32x128 transpose tile per CTA.
// ---------------------------------------------------------------------------
__global__ __launch_bounds__(128) void scan_final_kernel(float* __restrict__ out) {
    __shared__ float tile[32][129];
    int bc = blockIdx.x;
    int b = bc / NC;
    int c = bc % NC;
    int f = threadIdx.x;
    int lane = f & 31, wid = f >> 5;

    const __half* actb = g_actH + (size_t)(b * T_) * O_;
    const __half* Xfb  = g_Xf + (size_t)b * T_ * F_;

    float M = g_Ms[(b * NC + c) * F_ + f];
    int t0 = c * CHUNK;
    #pragma unroll 4
    for (int q = 0; q < CHUNK; q++) {
        int t = t0 + q;
        const __half* rowp = actb + (size_t)t * O_;
        float s     = __half2float(rowp[f]);
        float alpha = __half2float(rowp[128 + f]);
        float delta = __half2float(rowp[256 + f]);
        float r     = __half2float(rowp[384 + f]);
        float x = __half2float(Xfb[(size_t)t * F_ + f]);
        M = (1.f - s) * M + s * x;
        float base = x * __powf(M + EPS, -alpha) + delta;
        tile[q][f] = __powf(base, r) - __powf(delta, r);
    }
    __syncthreads();
    #pragma unroll
    for (int ff = wid; ff < 128; ff += 4)
        out[(size_t)(b * F_ + ff) * T_ + t0 + lane] = tile[lane][ff];
}

// ---------------------------------------------------------------------------
// Launch
// ---------------------------------------------------------------------------
extern "C" void kernel_launch(void* const* d_in, const int* in_sizes, int n_in,
                              void* d_out, int out_size) {
    const float* X  = (const float*)d_in[0];
    const float* W1 = (const float*)d_in[1];
    const float* b1 = (const float*)d_in[2];
    const float* W2 = (const float*)d_in[3];
    const float* b2 = (const float*)d_in[4];
    float* out = (float*)d_out;

    __half *Xf, *W1f, *W2f;
    cudaGetSymbolAddress((void**)&Xf,  g_Xf);
    cudaGetSymbolAddress((void**)&W1f, g_W1f);
    cudaGetSymbolAddress((void**)&W2f, g_W2f);

    // Idempotent host-side attribute sets (capture-safe)
    cudaFuncSetAttribute(fused_mlp, cudaFuncAttributeMaxDynamicSharedMemorySize, SMEM_FUSED);
    cudaFuncSetAttribute(scan_chain_kernel, cudaFuncAttributeMaxDynamicSharedMemorySize, CHAIN_SMEM);

    transpose_conv<<<dim3(T_ / 32, F_ / 32, B_), dim3(32, 8)>>>(X, Xf, F_, T_);
    transpose_w<<<dim3(O_ / 32, KDIM / 32, 2), dim3(32, 8)>>>(W1, W1f, W2, W2f);

    fused_mlp<<<(B_ * T_) / 128, 512, SMEM_FUSED>>>(b1, b2);   // 1000 CTAs

    scan_reduce_kernel<<<(B_ * NC * F_ / 2) / 256, 256>>>();   // 1000 CTAs
    scan_chain_kernel<<<B_, 128, CHAIN_SMEM>>>();
    scan_final_kernel<<<B_ * NC, 128>>>(out);
}